// round 1
// baseline (speedup 1.0000x reference)
#include <cuda_runtime.h>
#include <math.h>

#define BB 8
#define CC 64
#define OO 64
#define HH 96
#define WW 96
#define NN 9
#define HW (HH*WW)            // 9216
#define PIXELS (BB*HH*WW)     // 73728
#define SCR_CH 27

// scratch for offset (18) + modulation-raw (9) planes, layout [ch][pixel]
__device__ float g_scr[SCR_CH * PIXELS];

__device__ __forceinline__ unsigned long long pack2(float v) {
    unsigned long long r;
    unsigned u = __float_as_uint(v);
    asm("mov.b64 %0, {%1, %1};" : "=l"(r) : "r"(u));
    return r;
}
__device__ __forceinline__ void fma2(unsigned long long &acc,
                                     unsigned long long a,
                                     unsigned long long b) {
    asm("fma.rn.f32x2 %0, %1, %2, %0;" : "+l"(acc) : "l"(a), "l"(b));
}
__device__ __forceinline__ float lo32(unsigned long long v) {
    return __uint_as_float((unsigned)(v & 0xffffffffULL));
}
__device__ __forceinline__ float hi32(unsigned long long v) {
    return __uint_as_float((unsigned)(v >> 32));
}

// ---------------------------------------------------------------------------
// Kernel 1: 3x3 conv, 27 output channels (18 offset + 9 modulation), pad=1.
// Weights in SMEM as [c*9+k][28] (27 padded to 28 for ulonglong2 loads).
// Each thread computes 2 pixels (p and p + PIXELS/2) to amortize weight LDS.
// ---------------------------------------------------------------------------
__global__ void __launch_bounds__(256) k_offconv(
    const float* __restrict__ x,
    const float* __restrict__ ow, const float* __restrict__ ob,
    const float* __restrict__ mw, const float* __restrict__ mb)
{
    extern __shared__ float ws[];   // 576*28 floats = 64512 B
    const int tid = threadIdx.x;

    for (int i = tid; i < 576 * 28; i += 256) {
        int ck = i / 28, ch = i % 28;
        int c = ck / 9, k = ck % 9;
        float v = 0.f;
        if (ch < 18)      v = ow[(ch * CC + c) * 9 + k];
        else if (ch < 27) v = mw[((ch - 18) * CC + c) * 9 + k];
        ws[i] = v;
    }
    __syncthreads();

    const int p0 = blockIdx.x * 256 + tid;
    const int p1 = p0 + PIXELS / 2;

    const int b0 = p0 / HW, r0 = p0 % HW, h0 = r0 / WW, w0 = r0 % WW;
    const int b1 = p1 / HW, r1 = p1 % HW, h1 = r1 / WW, w1 = r1 % WW;

    // precompute per-tap source offsets (or -1 if in zero padding)
    int offA[9], offB[9];
    #pragma unroll
    for (int k = 0; k < 9; k++) {
        int dh = k / 3 - 1, dw = k % 3 - 1;
        int ihA = h0 + dh, iwA = w0 + dw;
        int ihB = h1 + dh, iwB = w1 + dw;
        offA[k] = ((unsigned)ihA < HH && (unsigned)iwA < WW) ? ihA * WW + iwA : -1;
        offB[k] = ((unsigned)ihB < HH && (unsigned)iwB < WW) ? ihB * WW + iwB : -1;
    }

    unsigned long long accA[14], accB[14];
    #pragma unroll
    for (int j = 0; j < 14; j++) { accA[j] = 0ULL; accB[j] = 0ULL; }

    const float* xa = x + (size_t)b0 * CC * HW;
    const float* xb = x + (size_t)b1 * CC * HW;
    const ulonglong2* wbase = (const ulonglong2*)ws;

    #pragma unroll 1
    for (int c = 0; c < CC; c++) {
        const float* xac = xa + c * HW;
        const float* xbc = xb + c * HW;
        const ulonglong2* wc = wbase + c * 9 * 7;   // 28 floats = 7 ulonglong2 per tap
        #pragma unroll
        for (int k = 0; k < 9; k++) {
            float vA = (offA[k] >= 0) ? __ldg(xac + offA[k]) : 0.f;
            float vB = (offB[k] >= 0) ? __ldg(xbc + offB[k]) : 0.f;
            unsigned long long a2 = pack2(vA);
            unsigned long long b2 = pack2(vB);
            #pragma unroll
            for (int q = 0; q < 7; q++) {
                ulonglong2 wv = wc[k * 7 + q];
                fma2(accA[2 * q],     wv.x, a2);
                fma2(accA[2 * q + 1], wv.y, a2);
                fma2(accB[2 * q],     wv.x, b2);
                fma2(accB[2 * q + 1], wv.y, b2);
            }
        }
    }

    #pragma unroll
    for (int j = 0; j < 14; j++) {
        int ch0 = 2 * j, ch1 = 2 * j + 1;
        if (ch0 < 27) {
            float bias = (ch0 < 18) ? ob[ch0] : mb[ch0 - 18];
            g_scr[ch0 * PIXELS + p0] = lo32(accA[j]) + bias;
            g_scr[ch0 * PIXELS + p1] = lo32(accB[j]) + bias;
        }
        if (ch1 < 27) {
            float bias = (ch1 < 18) ? ob[ch1] : mb[ch1 - 18];
            g_scr[ch1 * PIXELS + p0] = hi32(accA[j]) + bias;
            g_scr[ch1 * PIXELS + p1] = hi32(accB[j]) + bias;
        }
    }
}

// ---------------------------------------------------------------------------
// Kernel 2: fused bilinear deformable sampling + [C*N] x [O] contraction.
// conv_w reordered to [c][n][o] in SMEM (o contiguous -> broadcast LDS.128).
// One pixel per thread, 64 outputs as 32 packed f32x2 accumulators.
// Zero-padding folded into coefficients (coef=0, addr=0).
// ---------------------------------------------------------------------------
__global__ void __launch_bounds__(512) k_deform(
    const float* __restrict__ x,
    const float* __restrict__ cw, const float* __restrict__ cb,
    float* __restrict__ out)
{
    extern __shared__ float ws[];   // 64*9*64 floats = 147456 B
    const int tid = threadIdx.x;

    for (int i = tid; i < CC * NN * OO; i += 512) {
        int o = i % OO;
        int cn = i / OO;
        int c = cn / NN, n = cn % NN;
        ws[i] = cw[(o * CC + c) * NN + n];
    }
    __syncthreads();

    const int p = blockIdx.x * 512 + tid;
    const int b = p / HW, r = p % HW;
    const int h = r / WW, w = r % WW;

    unsigned long long acc[32];
    #pragma unroll
    for (int q = 0; q < 32; q++) acc[q] = 0ULL;

    const float* xb = x + (size_t)b * CC * HW;

    #pragma unroll 1
    for (int n = 0; n < NN; n++) {
        float offx = g_scr[n * PIXELS + p];
        float offy = g_scr[(9 + n) * PIXELS + p];
        float mraw = g_scr[(18 + n) * PIXELS + p];
        float m = 1.f / (1.f + __expf(-mraw));

        float px = offx + (float)(h + 1) + (float)(n / 3 - 1);
        float py = offy + (float)(w + 1) + (float)(n % 3 - 1);

        float flx = floorf(px), fly = floorf(py);
        int tlx = max(min((int)flx, 97), 0);
        int brx = max(min((int)flx + 1, 97), 0);
        int tly = max(min((int)fly, 97), 0);
        int bry = max(min((int)fly + 1, 97), 0);
        float pcx = fminf(fmaxf(px, 0.f), 97.f);
        float pcy = fminf(fmaxf(py, 0.f), 97.f);

        float axt = 1.f + ((float)tlx - pcx);
        float axb = 1.f - ((float)brx - pcx);
        float ayt = 1.f + ((float)tly - pcy);
        float ayb = 1.f - ((float)bry - pcy);

        float c_tl = axt * ayt * m;
        float c_tr = axt * ayb * m;
        float c_bl = axb * ayt * m;
        float c_br = axb * ayb * m;

        // padded coord (ix,iy) maps to interior x[ix-1][iy-1]; border = 0
        bool vtx = (tlx >= 1 && tlx <= 96);
        bool vbx = (brx >= 1 && brx <= 96);
        bool vty = (tly >= 1 && tly <= 96);
        bool vby = (bry >= 1 && bry <= 96);

        int a_tl = (tlx - 1) * WW + (tly - 1);
        int a_tr = (tlx - 1) * WW + (bry - 1);
        int a_bl = (brx - 1) * WW + (tly - 1);
        int a_br = (brx - 1) * WW + (bry - 1);
        if (!(vtx && vty)) { c_tl = 0.f; a_tl = 0; }
        if (!(vtx && vby)) { c_tr = 0.f; a_tr = 0; }
        if (!(vbx && vty)) { c_bl = 0.f; a_bl = 0; }
        if (!(vbx && vby)) { c_br = 0.f; a_br = 0; }

        const float* xc = xb;
        const ulonglong2* wp = (const ulonglong2*)(ws + n * OO);
        #pragma unroll 1
        for (int c = 0; c < CC; c++) {
            float v = c_tl * __ldg(xc + a_tl) + c_tr * __ldg(xc + a_tr)
                    + c_bl * __ldg(xc + a_bl) + c_br * __ldg(xc + a_br);
            unsigned long long v2 = pack2(v);
            #pragma unroll
            for (int q = 0; q < 16; q++) {
                ulonglong2 wv = wp[q];
                fma2(acc[2 * q],     wv.x, v2);
                fma2(acc[2 * q + 1], wv.y, v2);
            }
            xc += HW;
            wp += (NN * OO) / 4;   // 576 floats = 144 ulonglong2 per c
        }
    }

    float* op = out + (size_t)b * OO * HW + h * WW + w;
    #pragma unroll
    for (int q = 0; q < 32; q++) {
        int o0 = 2 * q, o1 = o0 + 1;
        op[(size_t)o0 * HW] = lo32(acc[q]) + cb[o0];
        op[(size_t)o1 * HW] = hi32(acc[q]) + cb[o1];
    }
}

extern "C" void kernel_launch(void* const* d_in, const int* in_sizes, int n_in,
                              void* d_out, int out_size) {
    const float* x  = (const float*)d_in[0];
    const float* ow = (const float*)d_in[1];
    const float* ob = (const float*)d_in[2];
    const float* mw = (const float*)d_in[3];
    const float* mb = (const float*)d_in[4];
    const float* cw = (const float*)d_in[5];
    const float* cb = (const float*)d_in[6];
    float* out = (float*)d_out;

    const int smem1 = 576 * 28 * 4;          // 64512 B
    const int smem2 = CC * NN * OO * 4;      // 147456 B
    cudaFuncSetAttribute(k_offconv, cudaFuncAttributeMaxDynamicSharedMemorySize, smem1);
    cudaFuncSetAttribute(k_deform,  cudaFuncAttributeMaxDynamicSharedMemorySize, smem2);

    k_offconv<<<(PIXELS / 2) / 256, 256, smem1>>>(x, ow, ob, mw, mb);
    k_deform<<<PIXELS / 512, 512, smem2>>>(x, cw, cb, out);
}

// round 2
// speedup vs baseline: 1.0677x; 1.0677x over previous
#include <cuda_runtime.h>
#include <math.h>

#define BB 8
#define CC 64
#define OO 64
#define HH 96
#define WW 96
#define NN 9
#define HW (HH*WW)            // 9216
#define PIXELS (BB*HH*WW)     // 73728
#define SCR_CH 27

// scratch for offset (18) + modulation-raw (9) planes, layout [ch][pixel]
__device__ float g_scr[SCR_CH * PIXELS];

__device__ __forceinline__ unsigned long long pack2(float v) {
    unsigned long long r;
    unsigned u = __float_as_uint(v);
    asm("mov.b64 %0, {%1, %1};" : "=l"(r) : "r"(u));
    return r;
}
__device__ __forceinline__ void fma2(unsigned long long &acc,
                                     unsigned long long a,
                                     unsigned long long b) {
    asm("fma.rn.f32x2 %0, %1, %2, %0;" : "+l"(acc) : "l"(a), "l"(b));
}
__device__ __forceinline__ float lo32(unsigned long long v) {
    return __uint_as_float((unsigned)(v & 0xffffffffULL));
}
__device__ __forceinline__ float hi32(unsigned long long v) {
    return __uint_as_float((unsigned)(v >> 32));
}

// ---------------------------------------------------------------------------
// Kernel 1: 3x3 conv, 27 output channels (18 offset + 9 modulation), pad=1.
// (unchanged from round 1 — ~51us, FMA-bound-ish, not the bottleneck)
// ---------------------------------------------------------------------------
__global__ void __launch_bounds__(256) k_offconv(
    const float* __restrict__ x,
    const float* __restrict__ ow, const float* __restrict__ ob,
    const float* __restrict__ mw, const float* __restrict__ mb)
{
    extern __shared__ float ws[];   // 576*28 floats = 64512 B
    const int tid = threadIdx.x;

    for (int i = tid; i < 576 * 28; i += 256) {
        int ck = i / 28, ch = i % 28;
        int c = ck / 9, k = ck % 9;
        float v = 0.f;
        if (ch < 18)      v = ow[(ch * CC + c) * 9 + k];
        else if (ch < 27) v = mw[((ch - 18) * CC + c) * 9 + k];
        ws[i] = v;
    }
    __syncthreads();

    const int p0 = blockIdx.x * 256 + tid;
    const int p1 = p0 + PIXELS / 2;

    const int b0 = p0 / HW, r0 = p0 % HW, h0 = r0 / WW, w0 = r0 % WW;
    const int b1 = p1 / HW, r1 = p1 % HW, h1 = r1 / WW, w1 = r1 % WW;

    int offA[9], offB[9];
    #pragma unroll
    for (int k = 0; k < 9; k++) {
        int dh = k / 3 - 1, dw = k % 3 - 1;
        int ihA = h0 + dh, iwA = w0 + dw;
        int ihB = h1 + dh, iwB = w1 + dw;
        offA[k] = ((unsigned)ihA < HH && (unsigned)iwA < WW) ? ihA * WW + iwA : -1;
        offB[k] = ((unsigned)ihB < HH && (unsigned)iwB < WW) ? ihB * WW + iwB : -1;
    }

    unsigned long long accA[14], accB[14];
    #pragma unroll
    for (int j = 0; j < 14; j++) { accA[j] = 0ULL; accB[j] = 0ULL; }

    const float* xa = x + (size_t)b0 * CC * HW;
    const float* xb = x + (size_t)b1 * CC * HW;
    const ulonglong2* wbase = (const ulonglong2*)ws;

    #pragma unroll 1
    for (int c = 0; c < CC; c++) {
        const float* xac = xa + c * HW;
        const float* xbc = xb + c * HW;
        const ulonglong2* wc = wbase + c * 9 * 7;
        #pragma unroll
        for (int k = 0; k < 9; k++) {
            float vA = (offA[k] >= 0) ? __ldg(xac + offA[k]) : 0.f;
            float vB = (offB[k] >= 0) ? __ldg(xbc + offB[k]) : 0.f;
            unsigned long long a2 = pack2(vA);
            unsigned long long b2 = pack2(vB);
            #pragma unroll
            for (int q = 0; q < 7; q++) {
                ulonglong2 wv = wc[k * 7 + q];
                fma2(accA[2 * q],     wv.x, a2);
                fma2(accA[2 * q + 1], wv.y, a2);
                fma2(accB[2 * q],     wv.x, b2);
                fma2(accB[2 * q + 1], wv.y, b2);
            }
        }
    }

    #pragma unroll
    for (int j = 0; j < 14; j++) {
        int ch0 = 2 * j, ch1 = 2 * j + 1;
        if (ch0 < 27) {
            float bias = (ch0 < 18) ? ob[ch0] : mb[ch0 - 18];
            g_scr[ch0 * PIXELS + p0] = lo32(accA[j]) + bias;
            g_scr[ch0 * PIXELS + p1] = lo32(accB[j]) + bias;
        }
        if (ch1 < 27) {
            float bias = (ch1 < 18) ? ob[ch1] : mb[ch1 - 18];
            g_scr[ch1 * PIXELS + p0] = hi32(accA[j]) + bias;
            g_scr[ch1 * PIXELS + p1] = hi32(accB[j]) + bias;
        }
    }
}

// ---------------------------------------------------------------------------
// Kernel 2 (v2): fused bilinear sampling + contraction.
//   - Each lane gathers ONE pixel's bilinear value (4 LDG), then a single
//     shfl.xor(16) exchanges it so every thread holds 2 pixels' values.
//   - Lane halves split the 64 outputs (32 each); weight copies for the two
//     halves live at smem offsets differing by 16 floats mod 32 banks, so the
//     two broadcast LDS.128 addresses hit disjoint banks -> 1 wavefront.
//   - LDS wavefronts per (n,c) per 32 pixels: 16 -> 8. FMA unchanged.
//   - Gathers software-pipelined 2 channels ahead (MLP~8) because occupancy
//     is 8 warps/SM (147KB smem -> 1 CTA of 256 threads).
// ---------------------------------------------------------------------------
#define GOFF (CC * NN * 32 + 16)   // 18448 floats between weight groups

__global__ void __launch_bounds__(256) k_deform(
    const float* __restrict__ x,
    const float* __restrict__ cw, const float* __restrict__ cb,
    float* __restrict__ out)
{
    extern __shared__ float ws[];   // 2 groups: (18432 + 16) + 18432 = 147520 B
    const int tid = threadIdx.x;

    for (int i = tid; i < CC * NN * OO; i += 256) {
        int o = i % OO;
        int cn = i / OO;
        int c = cn / NN, n = cn % NN;
        int g = o >> 5, oo = o & 31;
        ws[g * GOFF + (c * NN + n) * 32 + oo] = cw[(o * CC + c) * NN + n];
    }
    __syncthreads();

    const int lane = tid & 31;
    const int wid  = tid >> 5;
    const int half = lane >> 4;      // 0: outputs [0,32), 1: [32,64)
    const int l16  = lane & 15;

    // gather pixel for this lane
    const int pg = blockIdx.x * 256 + wid * 32 + lane;
    const int bg = pg / HW, rg = pg % HW;
    const int hg = rg / WW, wg = rg % WW;
    const float* xg = x + (size_t)bg * CC * HW;

    unsigned long long accA[16], accB[16];
    #pragma unroll
    for (int q = 0; q < 16; q++) { accA[q] = 0ULL; accB[q] = 0ULL; }

    const float* wt = ws + half * GOFF;   // this thread's weight group base

    #pragma unroll 1
    for (int n = 0; n < NN; n++) {
        float offx = g_scr[n * PIXELS + pg];
        float offy = g_scr[(9 + n) * PIXELS + pg];
        float mraw = g_scr[(18 + n) * PIXELS + pg];
        float m = 1.f / (1.f + __expf(-mraw));

        float px = offx + (float)(hg + 1) + (float)(n / 3 - 1);
        float py = offy + (float)(wg + 1) + (float)(n % 3 - 1);

        float flx = floorf(px), fly = floorf(py);
        int tlx = max(min((int)flx, 97), 0);
        int brx = max(min((int)flx + 1, 97), 0);
        int tly = max(min((int)fly, 97), 0);
        int bry = max(min((int)fly + 1, 97), 0);
        float pcx = fminf(fmaxf(px, 0.f), 97.f);
        float pcy = fminf(fmaxf(py, 0.f), 97.f);

        float axt = 1.f + ((float)tlx - pcx);
        float axb = 1.f - ((float)brx - pcx);
        float ayt = 1.f + ((float)tly - pcy);
        float ayb = 1.f - ((float)bry - pcy);

        float c_tl = axt * ayt * m;
        float c_tr = axt * ayb * m;
        float c_bl = axb * ayt * m;
        float c_br = axb * ayb * m;

        bool vtx = (tlx >= 1 && tlx <= 96);
        bool vbx = (brx >= 1 && brx <= 96);
        bool vty = (tly >= 1 && tly <= 96);
        bool vby = (bry >= 1 && bry <= 96);

        int a_tl = (tlx - 1) * WW + (tly - 1);
        int a_tr = (tlx - 1) * WW + (bry - 1);
        int a_bl = (brx - 1) * WW + (tly - 1);
        int a_br = (brx - 1) * WW + (bry - 1);
        if (!(vtx && vty)) { c_tl = 0.f; a_tl = 0; }
        if (!(vtx && vby)) { c_tr = 0.f; a_tr = 0; }
        if (!(vbx && vty)) { c_bl = 0.f; a_bl = 0; }
        if (!(vbx && vby)) { c_br = 0.f; a_br = 0; }

        // software pipeline: keep 2 channels of corner loads in flight
        float p0[4], p1[4];
        p0[0] = __ldg(xg + a_tl); p0[1] = __ldg(xg + a_tr);
        p0[2] = __ldg(xg + a_bl); p0[3] = __ldg(xg + a_br);
        const float* x1 = xg + HW;
        p1[0] = __ldg(x1 + a_tl); p1[1] = __ldg(x1 + a_tr);
        p1[2] = __ldg(x1 + a_bl); p1[3] = __ldg(x1 + a_br);

        const ulonglong2* wp = (const ulonglong2*)(wt + n * 32);
        const int wstep = (NN * 32) / 4;            // ulonglong2 per channel

        #pragma unroll 1
        for (int c = 0; c < CC; c += 2) {
            // ---- channel c: prefetch c+2, consume p0 ----
            const float* xpf = xg + (c + 2 < CC ? (c + 2) : 0) * HW;
            float q0[4];
            q0[0] = __ldg(xpf + a_tl); q0[1] = __ldg(xpf + a_tr);
            q0[2] = __ldg(xpf + a_bl); q0[3] = __ldg(xpf + a_br);

            {
                float vgath = c_tl * p0[0] + c_tr * p0[1]
                            + c_bl * p0[2] + c_br * p0[3];
                float voth = __shfl_xor_sync(0xffffffffu, vgath, 16);
                float vAf = half ? voth : vgath;
                float vBf = half ? vgath : voth;
                unsigned long long vA = pack2(vAf);
                unsigned long long vB = pack2(vBf);
                #pragma unroll
                for (int q = 0; q < 8; q++) {
                    ulonglong2 wv = wp[q];
                    fma2(accA[2 * q],     wv.x, vA);
                    fma2(accA[2 * q + 1], wv.y, vA);
                    fma2(accB[2 * q],     wv.x, vB);
                    fma2(accB[2 * q + 1], wv.y, vB);
                }
                wp += wstep;
            }

            // ---- channel c+1: prefetch c+3, consume p1 ----
            const float* xpf2 = xg + (c + 3 < CC ? (c + 3) : 0) * HW;
            float q1[4];
            q1[0] = __ldg(xpf2 + a_tl); q1[1] = __ldg(xpf2 + a_tr);
            q1[2] = __ldg(xpf2 + a_bl); q1[3] = __ldg(xpf2 + a_br);

            {
                float vgath = c_tl * p1[0] + c_tr * p1[1]
                            + c_bl * p1[2] + c_br * p1[3];
                float voth = __shfl_xor_sync(0xffffffffu, vgath, 16);
                float vAf = half ? voth : vgath;
                float vBf = half ? vgath : voth;
                unsigned long long vA = pack2(vAf);
                unsigned long long vB = pack2(vBf);
                #pragma unroll
                for (int q = 0; q < 8; q++) {
                    ulonglong2 wv = wp[q];
                    fma2(accA[2 * q],     wv.x, vA);
                    fma2(accA[2 * q + 1], wv.y, vA);
                    fma2(accB[2 * q],     wv.x, vB);
                    fma2(accB[2 * q + 1], wv.y, vB);
                }
                wp += wstep;
            }

            #pragma unroll
            for (int j = 0; j < 4; j++) { p0[j] = q0[j]; p1[j] = q1[j]; }
        }
    }

    // epilogue: thread writes outputs [32*half, 32*half+32) for pixels pA, pB
    const int pA = blockIdx.x * 256 + wid * 32 + l16;
    const int pB = pA + 16;
    const int bA = pA / HW, rA = pA % HW;
    const int bB = pB / HW, rB = pB % HW;
    float* opA = out + (size_t)bA * OO * HW + (size_t)(half * 32) * HW + rA;
    float* opB = out + (size_t)bB * OO * HW + (size_t)(half * 32) * HW + rB;
    #pragma unroll
    for (int q = 0; q < 16; q++) {
        int o0 = 2 * q, o1 = o0 + 1;
        float b0 = cb[half * 32 + o0];
        float b1 = cb[half * 32 + o1];
        opA[(size_t)o0 * HW] = lo32(accA[q]) + b0;
        opA[(size_t)o1 * HW] = hi32(accA[q]) + b1;
        opB[(size_t)o0 * HW] = lo32(accB[q]) + b0;
        opB[(size_t)o1 * HW] = hi32(accB[q]) + b1;
    }
}

extern "C" void kernel_launch(void* const* d_in, const int* in_sizes, int n_in,
                              void* d_out, int out_size) {
    const float* x  = (const float*)d_in[0];
    const float* ow = (const float*)d_in[1];
    const float* ob = (const float*)d_in[2];
    const float* mw = (const float*)d_in[3];
    const float* mb = (const float*)d_in[4];
    const float* cw = (const float*)d_in[5];
    const float* cb = (const float*)d_in[6];
    float* out = (float*)d_out;

    const int smem1 = 576 * 28 * 4;           // 64512 B
    const int smem2 = (GOFF + CC * NN * 32) * 4;  // 147520 B
    cudaFuncSetAttribute(k_offconv, cudaFuncAttributeMaxDynamicSharedMemorySize, smem1);
    cudaFuncSetAttribute(k_deform,  cudaFuncAttributeMaxDynamicSharedMemorySize, smem2);

    k_offconv<<<(PIXELS / 2) / 256, 256, smem1>>>(x, ow, ob, mw, mb);
    k_deform<<<PIXELS / 256, 256, smem2>>>(x, cw, cb, out);
}

// round 4
// speedup vs baseline: 1.0806x; 1.0121x over previous
#include <cuda_runtime.h>
#include <math.h>

#define BB 8
#define CC 64
#define OO 64
#define HH 96
#define WW 96
#define NN 9
#define HW (HH*WW)            // 9216
#define PIXELS (BB*HH*WW)     // 73728
#define SCR_CH 27
#define CH 32                 // channels per K-split

// scratch for offset (18) + modulation-raw (9) planes, layout [ch][pixel]
__device__ float g_scr[SCR_CH * PIXELS];
// partial sums from the second K-split half
__device__ float g_part[PIXELS * OO];

__device__ __forceinline__ unsigned long long pack2(float v) {
    unsigned long long r;
    unsigned u = __float_as_uint(v);
    asm("mov.b64 %0, {%1, %1};" : "=l"(r) : "r"(u));
    return r;
}
__device__ __forceinline__ void fma2(unsigned long long &acc,
                                     unsigned long long a,
                                     unsigned long long b) {
    asm("fma.rn.f32x2 %0, %1, %2, %0;" : "+l"(acc) : "l"(a), "l"(b));
}
__device__ __forceinline__ float lo32(unsigned long long v) {
    return __uint_as_float((unsigned)(v & 0xffffffffULL));
}
__device__ __forceinline__ float hi32(unsigned long long v) {
    return __uint_as_float((unsigned)(v >> 32));
}

// ---------------------------------------------------------------------------
// Kernel 1: 3x3 conv, 27 output channels (18 offset + 9 modulation), pad=1.
// 128-thread CTAs -> 3 CTAs/SM for latency hiding.
// ---------------------------------------------------------------------------
__global__ void __launch_bounds__(128) k_offconv(
    const float* __restrict__ x,
    const float* __restrict__ ow, const float* __restrict__ ob,
    const float* __restrict__ mw, const float* __restrict__ mb)
{
    extern __shared__ float ws[];   // 576*28 floats = 64512 B
    const int tid = threadIdx.x;

    for (int i = tid; i < 576 * 28; i += 128) {
        int ck = i / 28, ch = i % 28;
        int c = ck / 9, k = ck % 9;
        float v = 0.f;
        if (ch < 18)      v = ow[(ch * CC + c) * 9 + k];
        else if (ch < 27) v = mw[((ch - 18) * CC + c) * 9 + k];
        ws[i] = v;
    }
    __syncthreads();

    const int p0 = blockIdx.x * 128 + tid;
    const int p1 = p0 + PIXELS / 2;

    const int b0 = p0 / HW, r0 = p0 % HW, h0 = r0 / WW, w0 = r0 % WW;
    const int b1 = p1 / HW, r1 = p1 % HW, h1 = r1 / WW, w1 = r1 % WW;

    int offA[9], offB[9];
    #pragma unroll
    for (int k = 0; k < 9; k++) {
        int dh = k / 3 - 1, dw = k % 3 - 1;
        int ihA = h0 + dh, iwA = w0 + dw;
        int ihB = h1 + dh, iwB = w1 + dw;
        offA[k] = ((unsigned)ihA < HH && (unsigned)iwA < WW) ? ihA * WW + iwA : -1;
        offB[k] = ((unsigned)ihB < HH && (unsigned)iwB < WW) ? ihB * WW + iwB : -1;
    }

    unsigned long long accA[14], accB[14];
    #pragma unroll
    for (int j = 0; j < 14; j++) { accA[j] = 0ULL; accB[j] = 0ULL; }

    const float* xa = x + (size_t)b0 * CC * HW;
    const float* xb = x + (size_t)b1 * CC * HW;
    const ulonglong2* wbase = (const ulonglong2*)ws;

    #pragma unroll 1
    for (int c = 0; c < CC; c++) {
        const float* xac = xa + c * HW;
        const float* xbc = xb + c * HW;
        const ulonglong2* wc = wbase + c * 9 * 7;
        #pragma unroll
        for (int k = 0; k < 9; k++) {
            float vA = (offA[k] >= 0) ? __ldg(xac + offA[k]) : 0.f;
            float vB = (offB[k] >= 0) ? __ldg(xbc + offB[k]) : 0.f;
            unsigned long long a2 = pack2(vA);
            unsigned long long b2 = pack2(vB);
            #pragma unroll
            for (int q = 0; q < 7; q++) {
                ulonglong2 wv = wc[k * 7 + q];
                fma2(accA[2 * q],     wv.x, a2);
                fma2(accA[2 * q + 1], wv.y, a2);
                fma2(accB[2 * q],     wv.x, b2);
                fma2(accB[2 * q + 1], wv.y, b2);
            }
        }
    }

    #pragma unroll
    for (int j = 0; j < 14; j++) {
        int ch0 = 2 * j, ch1 = 2 * j + 1;
        if (ch0 < 27) {
            float bias = (ch0 < 18) ? ob[ch0] : mb[ch0 - 18];
            g_scr[ch0 * PIXELS + p0] = lo32(accA[j]) + bias;
            g_scr[ch0 * PIXELS + p1] = lo32(accB[j]) + bias;
        }
        if (ch1 < 27) {
            float bias = (ch1 < 18) ? ob[ch1] : mb[ch1 - 18];
            g_scr[ch1 * PIXELS + p0] = hi32(accA[j]) + bias;
            g_scr[ch1 * PIXELS + p1] = hi32(accB[j]) + bias;
        }
    }
}

// ---------------------------------------------------------------------------
// Kernel 2 (v4): K-split fused bilinear sampling + contraction.
//   blockIdx.y in {0,1} selects channel half [c0, c0+32): 72KB weights
//   -> 2 CTAs/SM. Single plain-layout weight copy ws[(c*9+n)*64 + o].
//   Lane-half h reads its 32-float region (+32h) with chunk order rotated
//   by 4 (two base pointers wp+off / wp+4-off) so the two broadcast LDS.128
//   addresses hit disjoint bank groups (4q..4q+3 vs 4q+16..4q+19).
//   y=0 writes bias+partial to out; y=1 writes partial to g_part;
//   k_combine adds them. No atomics -> deterministic.
// ---------------------------------------------------------------------------
__global__ void __launch_bounds__(256, 2) k_deform(
    const float* __restrict__ x,
    const float* __restrict__ cw, const float* __restrict__ cb,
    float* __restrict__ out)
{
    extern __shared__ float ws[];   // CH*9*64 floats = 73728 B
    const int tid = threadIdx.x;
    const int c0 = blockIdx.y * CH;

    for (int i = tid; i < CH * NN * OO; i += 256) {
        int o = i & 63;
        int cn = i >> 6;                 // c_local*9 + n
        int c = cn / NN, n = cn % NN;
        ws[i] = cw[(o * CC + (c0 + c)) * NN + n];
    }
    __syncthreads();

    const int lane = tid & 31;
    const int wid  = tid >> 5;
    const int half = lane >> 4;      // output group [32*half, 32*half+32)
    const int l16  = lane & 15;
    const int off  = half * 4;       // chunk rotation (ulonglong2 units)

    const int pg = blockIdx.x * 256 + wid * 32 + lane;
    const int bg = pg / HW, rg = pg % HW;
    const int hg = rg / WW, wg = rg % WW;
    const float* xg = x + (size_t)bg * CC * HW + (size_t)c0 * HW;

    unsigned long long accA[16], accB[16];
    #pragma unroll
    for (int q = 0; q < 16; q++) { accA[q] = 0ULL; accB[q] = 0ULL; }

    #pragma unroll 1
    for (int n = 0; n < NN; n++) {
        float offx = g_scr[n * PIXELS + pg];
        float offy = g_scr[(9 + n) * PIXELS + pg];
        float mraw = g_scr[(18 + n) * PIXELS + pg];
        float m = 1.f / (1.f + __expf(-mraw));

        float px = offx + (float)(hg + 1) + (float)(n / 3 - 1);
        float py = offy + (float)(wg + 1) + (float)(n % 3 - 1);

        float flx = floorf(px), fly = floorf(py);
        int tlx = max(min((int)flx, 97), 0);
        int brx = max(min((int)flx + 1, 97), 0);
        int tly = max(min((int)fly, 97), 0);
        int bry = max(min((int)fly + 1, 97), 0);
        float pcx = fminf(fmaxf(px, 0.f), 97.f);
        float pcy = fminf(fmaxf(py, 0.f), 97.f);

        float axt = 1.f + ((float)tlx - pcx);
        float axb = 1.f - ((float)brx - pcx);
        float ayt = 1.f + ((float)tly - pcy);
        float ayb = 1.f - ((float)bry - pcy);

        float c_tl = axt * ayt * m;
        float c_tr = axt * ayb * m;
        float c_bl = axb * ayt * m;
        float c_br = axb * ayb * m;

        bool vtx = (tlx >= 1 && tlx <= 96);
        bool vbx = (brx >= 1 && brx <= 96);
        bool vty = (tly >= 1 && tly <= 96);
        bool vby = (bry >= 1 && bry <= 96);

        int a_tl = (tlx - 1) * WW + (tly - 1);
        int a_tr = (tlx - 1) * WW + (bry - 1);
        int a_bl = (brx - 1) * WW + (tly - 1);
        int a_br = (brx - 1) * WW + (bry - 1);
        if (!(vtx && vty)) { c_tl = 0.f; a_tl = 0; }
        if (!(vtx && vby)) { c_tr = 0.f; a_tr = 0; }
        if (!(vbx && vty)) { c_bl = 0.f; a_bl = 0; }
        if (!(vbx && vby)) { c_br = 0.f; a_br = 0; }

        const float* ptl = xg + a_tl;
        const float* ptr_ = xg + a_tr;
        const float* pbl = xg + a_bl;
        const float* pbr = xg + a_br;

        float p0[4], p1[4];
        p0[0] = __ldg(ptl);      p0[1] = __ldg(ptr_);
        p0[2] = __ldg(pbl);      p0[3] = __ldg(pbr);
        p1[0] = __ldg(ptl + HW); p1[1] = __ldg(ptr_ + HW);
        p1[2] = __ldg(pbl + HW); p1[3] = __ldg(pbr + HW);

        // this lane-half's 32-float region for kernel tap n, rotated chunk order
        const ulonglong2* wpP = (const ulonglong2*)ws + n * 16 + half * 8 + off;
        const ulonglong2* wpM = (const ulonglong2*)ws + n * 16 + half * 8 + 4 - off;
        const int wstep = (NN * OO) / 4;   // 144 ulonglong2 per channel

        #pragma unroll 1
        for (int c = 0; c < CH - 2; c += 2) {
            float q0[4], q1[4];
            q0[0] = __ldg(ptl + 2 * HW); q0[1] = __ldg(ptr_ + 2 * HW);
            q0[2] = __ldg(pbl + 2 * HW); q0[3] = __ldg(pbr + 2 * HW);

            {
                float vgath = c_tl * p0[0] + c_tr * p0[1]
                            + c_bl * p0[2] + c_br * p0[3];
                float voth = __shfl_xor_sync(0xffffffffu, vgath, 16);
                float vAf = half ? voth : vgath;
                float vBf = half ? vgath : voth;
                unsigned long long vA = pack2(vAf);
                unsigned long long vB = pack2(vBf);
                #pragma unroll
                for (int q = 0; q < 4; q++) {
                    ulonglong2 wv = wpP[q];
                    fma2(accA[2 * q],     wv.x, vA);
                    fma2(accA[2 * q + 1], wv.y, vA);
                    fma2(accB[2 * q],     wv.x, vB);
                    fma2(accB[2 * q + 1], wv.y, vB);
                }
                #pragma unroll
                for (int q = 4; q < 8; q++) {
                    ulonglong2 wv = wpM[q - 4];
                    fma2(accA[2 * q],     wv.x, vA);
                    fma2(accA[2 * q + 1], wv.y, vA);
                    fma2(accB[2 * q],     wv.x, vB);
                    fma2(accB[2 * q + 1], wv.y, vB);
                }
                wpP += wstep; wpM += wstep;
            }

            q1[0] = __ldg(ptl + 3 * HW); q1[1] = __ldg(ptr_ + 3 * HW);
            q1[2] = __ldg(pbl + 3 * HW); q1[3] = __ldg(pbr + 3 * HW);

            {
                float vgath = c_tl * p1[0] + c_tr * p1[1]
                            + c_bl * p1[2] + c_br * p1[3];
                float voth = __shfl_xor_sync(0xffffffffu, vgath, 16);
                float vAf = half ? voth : vgath;
                float vBf = half ? vgath : voth;
                unsigned long long vA = pack2(vAf);
                unsigned long long vB = pack2(vBf);
                #pragma unroll
                for (int q = 0; q < 4; q++) {
                    ulonglong2 wv = wpP[q];
                    fma2(accA[2 * q],     wv.x, vA);
                    fma2(accA[2 * q + 1], wv.y, vA);
                    fma2(accB[2 * q],     wv.x, vB);
                    fma2(accB[2 * q + 1], wv.y, vB);
                }
                #pragma unroll
                for (int q = 4; q < 8; q++) {
                    ulonglong2 wv = wpM[q - 4];
                    fma2(accA[2 * q],     wv.x, vA);
                    fma2(accA[2 * q + 1], wv.y, vA);
                    fma2(accB[2 * q],     wv.x, vB);
                    fma2(accB[2 * q + 1], wv.y, vB);
                }
                wpP += wstep; wpM += wstep;
            }

            #pragma unroll
            for (int j = 0; j < 4; j++) { p0[j] = q0[j]; p1[j] = q1[j]; }
            ptl += 2 * HW; ptr_ += 2 * HW; pbl += 2 * HW; pbr += 2 * HW;
        }

        // drain: last two channels (no prefetch)
        #pragma unroll
        for (int d = 0; d < 2; d++) {
            float* pv = d ? p1 : p0;
            float vgath = c_tl * pv[0] + c_tr * pv[1]
                        + c_bl * pv[2] + c_br * pv[3];
            float voth = __shfl_xor_sync(0xffffffffu, vgath, 16);
            float vAf = half ? voth : vgath;
            float vBf = half ? vgath : voth;
            unsigned long long vA = pack2(vAf);
            unsigned long long vB = pack2(vBf);
            #pragma unroll
            for (int q = 0; q < 4; q++) {
                ulonglong2 wv = wpP[q];
                fma2(accA[2 * q],     wv.x, vA);
                fma2(accA[2 * q + 1], wv.y, vA);
                fma2(accB[2 * q],     wv.x, vB);
                fma2(accB[2 * q + 1], wv.y, vB);
            }
            #pragma unroll
            for (int q = 4; q < 8; q++) {
                ulonglong2 wv = wpM[q - 4];
                fma2(accA[2 * q],     wv.x, vA);
                fma2(accA[2 * q + 1], wv.y, vA);
                fma2(accB[2 * q],     wv.x, vB);
                fma2(accB[2 * q + 1], wv.y, vB);
            }
            wpP += wstep; wpM += wstep;
        }
    }

    // epilogue: accumulator pair q holds outputs ob..ob+3,
    // ob = 32*half + 4*(q ^ (4*half)); y=0 adds bias -> out, y=1 -> g_part
    const int pA = blockIdx.x * 256 + wid * 32 + l16;
    const int pB = pA + 16;
    const int bA = pA / HW, rA = pA % HW;
    const int bB = pB / HW, rB = pB % HW;
    float* base = (c0 == 0) ? out : g_part;
    float* opA = base + (size_t)bA * OO * HW + rA;
    float* opB = base + (size_t)bB * OO * HW + rB;
    const int jx = half << 2;
    #pragma unroll
    for (int q = 0; q < 8; q++) {
        int ob = 32 * half + 4 * (q ^ jx);
        float b0 = 0.f, b1 = 0.f, b2 = 0.f, b3 = 0.f;
        if (c0 == 0) {
            b0 = cb[ob + 0]; b1 = cb[ob + 1];
            b2 = cb[ob + 2]; b3 = cb[ob + 3];
        }
        opA[(size_t)(ob + 0) * HW] = lo32(accA[2 * q])     + b0;
        opA[(size_t)(ob + 1) * HW] = hi32(accA[2 * q])     + b1;
        opA[(size_t)(ob + 2) * HW] = lo32(accA[2 * q + 1]) + b2;
        opA[(size_t)(ob + 3) * HW] = hi32(accA[2 * q + 1]) + b3;
        opB[(size_t)(ob + 0) * HW] = lo32(accB[2 * q])     + b0;
        opB[(size_t)(ob + 1) * HW] = hi32(accB[2 * q])     + b1;
        opB[(size_t)(ob + 2) * HW] = lo32(accB[2 * q + 1]) + b2;
        opB[(size_t)(ob + 3) * HW] = hi32(accB[2 * q + 1]) + b3;
    }
}

// ---------------------------------------------------------------------------
// Kernel 3: out += g_part  (vectorized, ~57MB traffic)
// ---------------------------------------------------------------------------
__global__ void __launch_bounds__(256) k_combine(float* __restrict__ out)
{
    int i = blockIdx.x * 256 + threadIdx.x;
    float4 a = ((float4*)out)[i];
    float4 b = ((const float4*)g_part)[i];
    a.x += b.x; a.y += b.y; a.z += b.z; a.w += b.w;
    ((float4*)out)[i] = a;
}

extern "C" void kernel_launch(void* const* d_in, const int* in_sizes, int n_in,
                              void* d_out, int out_size) {
    const float* x  = (const float*)d_in[0];
    const float* ow = (const float*)d_in[1];
    const float* ob = (const float*)d_in[2];
    const float* mw = (const float*)d_in[3];
    const float* mb = (const float*)d_in[4];
    const float* cw = (const float*)d_in[5];
    const float* cb = (const float*)d_in[6];
    float* out = (float*)d_out;

    const int smem1 = 576 * 28 * 4;          // 64512 B
    const int smem2 = CH * NN * OO * 4;      // 73728 B
    cudaFuncSetAttribute(k_offconv, cudaFuncAttributeMaxDynamicSharedMemorySize, smem1);
    cudaFuncSetAttribute(k_deform,  cudaFuncAttributeMaxDynamicSharedMemorySize, smem2);

    k_offconv<<<(PIXELS / 2) / 128, 128, smem1>>>(x, ow, ob, mw, mb);
    dim3 g2(PIXELS / 256, 2);
    k_deform<<<g2, 256, smem2>>>(x, cw, cb, out);
    k_combine<<<(PIXELS * OO / 4) / 256, 256>>>(out);
}

// round 5
// speedup vs baseline: 1.1444x; 1.0590x over previous
#include <cuda_runtime.h>
#include <math.h>

#define BB 8
#define CC 64
#define OO 64
#define HH 96
#define WW 96
#define NN 9
#define HW (HH*WW)            // 9216
#define PIXELS (BB*HH*WW)     // 73728
#define SCR_CH 27
#define CH 32                 // channels per K-split (both kernels)

// scratch planes [ch][pixel]: partial sums from the two channel halves
__device__ float g_scr [SCR_CH * PIXELS];   // half 0 (+bias)
__device__ float g_scr2[SCR_CH * PIXELS];   // half 1 (raw)
// partial sums of the main contraction, second channel half
__device__ float g_part[PIXELS * OO];

__device__ __forceinline__ unsigned long long pack2(float v) {
    unsigned long long r;
    unsigned u = __float_as_uint(v);
    asm("mov.b64 %0, {%1, %1};" : "=l"(r) : "r"(u));
    return r;
}
__device__ __forceinline__ void fma2(unsigned long long &acc,
                                     unsigned long long a,
                                     unsigned long long b) {
    asm("fma.rn.f32x2 %0, %1, %2, %0;" : "+l"(acc) : "l"(a), "l"(b));
}
__device__ __forceinline__ float lo32(unsigned long long v) {
    return __uint_as_float((unsigned)(v & 0xffffffffULL));
}
__device__ __forceinline__ float hi32(unsigned long long v) {
    return __uint_as_float((unsigned)(v >> 32));
}

// ---------------------------------------------------------------------------
// Kernel 1 (v5): 3x3 conv, 27 outputs, K-split over channel halves.
// blockIdx.y selects c in [32y, 32y+32). smem 32.25KB, 4 CTAs/SM -> 16 warps.
// ---------------------------------------------------------------------------
__global__ void __launch_bounds__(128, 4) k_offconv(
    const float* __restrict__ x,
    const float* __restrict__ ow, const float* __restrict__ ob,
    const float* __restrict__ mw, const float* __restrict__ mb)
{
    extern __shared__ float ws[];   // 288*28 floats = 32256 B
    const int tid = threadIdx.x;
    const int c0 = blockIdx.y * CH;

    for (int i = tid; i < CH * 9 * 28; i += 128) {
        int ck = i / 28, ch = i % 28;
        int c = ck / 9, k = ck % 9;
        float v = 0.f;
        if (ch < 18)      v = ow[(ch * CC + c0 + c) * 9 + k];
        else if (ch < 27) v = mw[((ch - 18) * CC + c0 + c) * 9 + k];
        ws[i] = v;
    }
    __syncthreads();

    const int p0 = blockIdx.x * 128 + tid;
    const int p1 = p0 + PIXELS / 2;

    const int b0 = p0 / HW, r0 = p0 % HW, h0 = r0 / WW, w0 = r0 % WW;
    const int b1 = p1 / HW, r1 = p1 % HW, h1 = r1 / WW, w1 = r1 % WW;

    int offA[9], offB[9];
    #pragma unroll
    for (int k = 0; k < 9; k++) {
        int dh = k / 3 - 1, dw = k % 3 - 1;
        int ihA = h0 + dh, iwA = w0 + dw;
        int ihB = h1 + dh, iwB = w1 + dw;
        offA[k] = ((unsigned)ihA < HH && (unsigned)iwA < WW) ? ihA * WW + iwA : -1;
        offB[k] = ((unsigned)ihB < HH && (unsigned)iwB < WW) ? ihB * WW + iwB : -1;
    }

    unsigned long long accA[14], accB[14];
    #pragma unroll
    for (int j = 0; j < 14; j++) { accA[j] = 0ULL; accB[j] = 0ULL; }

    const float* xa = x + (size_t)b0 * CC * HW + (size_t)c0 * HW;
    const float* xb = x + (size_t)b1 * CC * HW + (size_t)c0 * HW;
    const ulonglong2* wbase = (const ulonglong2*)ws;

    #pragma unroll 1
    for (int c = 0; c < CH; c++) {
        const float* xac = xa + c * HW;
        const float* xbc = xb + c * HW;
        const ulonglong2* wc = wbase + c * 9 * 7;
        #pragma unroll
        for (int k = 0; k < 9; k++) {
            float vA = (offA[k] >= 0) ? __ldg(xac + offA[k]) : 0.f;
            float vB = (offB[k] >= 0) ? __ldg(xbc + offB[k]) : 0.f;
            unsigned long long a2 = pack2(vA);
            unsigned long long b2 = pack2(vB);
            #pragma unroll
            for (int q = 0; q < 7; q++) {
                ulonglong2 wv = wc[k * 7 + q];
                fma2(accA[2 * q],     wv.x, a2);
                fma2(accA[2 * q + 1], wv.y, a2);
                fma2(accB[2 * q],     wv.x, b2);
                fma2(accB[2 * q + 1], wv.y, b2);
            }
        }
    }

    float* dst = (c0 == 0) ? g_scr : g_scr2;
    #pragma unroll
    for (int j = 0; j < 14; j++) {
        int ch0 = 2 * j, ch1 = 2 * j + 1;
        if (ch0 < 27) {
            float bias = 0.f;
            if (c0 == 0) bias = (ch0 < 18) ? ob[ch0] : mb[ch0 - 18];
            dst[ch0 * PIXELS + p0] = lo32(accA[j]) + bias;
            dst[ch0 * PIXELS + p1] = lo32(accB[j]) + bias;
        }
        if (ch1 < 27) {
            float bias = 0.f;
            if (c0 == 0) bias = (ch1 < 18) ? ob[ch1] : mb[ch1 - 18];
            dst[ch1 * PIXELS + p0] = hi32(accA[j]) + bias;
            dst[ch1 * PIXELS + p1] = hi32(accB[j]) + bias;
        }
    }
}

// ---------------------------------------------------------------------------
// Kernel 2 (v5): K-split fused bilinear sampling + contraction.
// Same as round 4 (correct rotated single-copy weights, 2 CTAs/SM), plus:
//   - offset/mod read as g_scr + g_scr2 (folded offconv combine)
//   - both prefetch corner sets issued at block top (deeper MLP)
// ---------------------------------------------------------------------------
__global__ void __launch_bounds__(256, 2) k_deform(
    const float* __restrict__ x,
    const float* __restrict__ cw, const float* __restrict__ cb,
    float* __restrict__ out)
{
    extern __shared__ float ws[];   // CH*9*64 floats = 73728 B
    const int tid = threadIdx.x;
    const int c0 = blockIdx.y * CH;

    for (int i = tid; i < CH * NN * OO; i += 256) {
        int o = i & 63;
        int cn = i >> 6;                 // c_local*9 + n
        int c = cn / NN, n = cn % NN;
        ws[i] = cw[(o * CC + (c0 + c)) * NN + n];
    }
    __syncthreads();

    const int lane = tid & 31;
    const int wid  = tid >> 5;
    const int half = lane >> 4;      // output group [32*half, 32*half+32)
    const int l16  = lane & 15;
    const int off  = half * 4;       // chunk rotation (ulonglong2 units)

    const int pg = blockIdx.x * 256 + wid * 32 + lane;
    const int bg = pg / HW, rg = pg % HW;
    const int hg = rg / WW, wg = rg % WW;
    const float* xg = x + (size_t)bg * CC * HW + (size_t)c0 * HW;

    unsigned long long accA[16], accB[16];
    #pragma unroll
    for (int q = 0; q < 16; q++) { accA[q] = 0ULL; accB[q] = 0ULL; }

    #pragma unroll 1
    for (int n = 0; n < NN; n++) {
        float offx = g_scr[n * PIXELS + pg]        + g_scr2[n * PIXELS + pg];
        float offy = g_scr[(9 + n) * PIXELS + pg]  + g_scr2[(9 + n) * PIXELS + pg];
        float mraw = g_scr[(18 + n) * PIXELS + pg] + g_scr2[(18 + n) * PIXELS + pg];
        float m = 1.f / (1.f + __expf(-mraw));

        float px = offx + (float)(hg + 1) + (float)(n / 3 - 1);
        float py = offy + (float)(wg + 1) + (float)(n % 3 - 1);

        float flx = floorf(px), fly = floorf(py);
        int tlx = max(min((int)flx, 97), 0);
        int brx = max(min((int)flx + 1, 97), 0);
        int tly = max(min((int)fly, 97), 0);
        int bry = max(min((int)fly + 1, 97), 0);
        float pcx = fminf(fmaxf(px, 0.f), 97.f);
        float pcy = fminf(fmaxf(py, 0.f), 97.f);

        float axt = 1.f + ((float)tlx - pcx);
        float axb = 1.f - ((float)brx - pcx);
        float ayt = 1.f + ((float)tly - pcy);
        float ayb = 1.f - ((float)bry - pcy);

        float c_tl = axt * ayt * m;
        float c_tr = axt * ayb * m;
        float c_bl = axb * ayt * m;
        float c_br = axb * ayb * m;

        bool vtx = (tlx >= 1 && tlx <= 96);
        bool vbx = (brx >= 1 && brx <= 96);
        bool vty = (tly >= 1 && tly <= 96);
        bool vby = (bry >= 1 && bry <= 96);

        int a_tl = (tlx - 1) * WW + (tly - 1);
        int a_tr = (tlx - 1) * WW + (bry - 1);
        int a_bl = (brx - 1) * WW + (tly - 1);
        int a_br = (brx - 1) * WW + (bry - 1);
        if (!(vtx && vty)) { c_tl = 0.f; a_tl = 0; }
        if (!(vtx && vby)) { c_tr = 0.f; a_tr = 0; }
        if (!(vbx && vty)) { c_bl = 0.f; a_bl = 0; }
        if (!(vbx && vby)) { c_br = 0.f; a_br = 0; }

        const float* ptl = xg + a_tl;
        const float* ptr_ = xg + a_tr;
        const float* pbl = xg + a_bl;
        const float* pbr = xg + a_br;

        float p0[4], p1[4];
        p0[0] = __ldg(ptl);      p0[1] = __ldg(ptr_);
        p0[2] = __ldg(pbl);      p0[3] = __ldg(pbr);
        p1[0] = __ldg(ptl + HW); p1[1] = __ldg(ptr_ + HW);
        p1[2] = __ldg(pbl + HW); p1[3] = __ldg(pbr + HW);

        const ulonglong2* wpP = (const ulonglong2*)ws + n * 16 + half * 8 + off;
        const ulonglong2* wpM = (const ulonglong2*)ws + n * 16 + half * 8 + 4 - off;
        const int wstep = (NN * OO) / 4;   // 144 ulonglong2 per channel

        #pragma unroll 1
        for (int c = 0; c < CH - 2; c += 2) {
            // prefetch BOTH next-next channels up front (8 LDGs in flight)
            float q0[4], q1[4];
            q0[0] = __ldg(ptl + 2 * HW); q0[1] = __ldg(ptr_ + 2 * HW);
            q0[2] = __ldg(pbl + 2 * HW); q0[3] = __ldg(pbr + 2 * HW);
            q1[0] = __ldg(ptl + 3 * HW); q1[1] = __ldg(ptr_ + 3 * HW);
            q1[2] = __ldg(pbl + 3 * HW); q1[3] = __ldg(pbr + 3 * HW);

            {
                float vgath = c_tl * p0[0] + c_tr * p0[1]
                            + c_bl * p0[2] + c_br * p0[3];
                float voth = __shfl_xor_sync(0xffffffffu, vgath, 16);
                float vAf = half ? voth : vgath;
                float vBf = half ? vgath : voth;
                unsigned long long vA = pack2(vAf);
                unsigned long long vB = pack2(vBf);
                #pragma unroll
                for (int q = 0; q < 4; q++) {
                    ulonglong2 wv = wpP[q];
                    fma2(accA[2 * q],     wv.x, vA);
                    fma2(accA[2 * q + 1], wv.y, vA);
                    fma2(accB[2 * q],     wv.x, vB);
                    fma2(accB[2 * q + 1], wv.y, vB);
                }
                #pragma unroll
                for (int q = 4; q < 8; q++) {
                    ulonglong2 wv = wpM[q - 4];
                    fma2(accA[2 * q],     wv.x, vA);
                    fma2(accA[2 * q + 1], wv.y, vA);
                    fma2(accB[2 * q],     wv.x, vB);
                    fma2(accB[2 * q + 1], wv.y, vB);
                }
                wpP += wstep; wpM += wstep;
            }
            {
                float vgath = c_tl * p1[0] + c_tr * p1[1]
                            + c_bl * p1[2] + c_br * p1[3];
                float voth = __shfl_xor_sync(0xffffffffu, vgath, 16);
                float vAf = half ? voth : vgath;
                float vBf = half ? vgath : voth;
                unsigned long long vA = pack2(vAf);
                unsigned long long vB = pack2(vBf);
                #pragma unroll
                for (int q = 0; q < 4; q++) {
                    ulonglong2 wv = wpP[q];
                    fma2(accA[2 * q],     wv.x, vA);
                    fma2(accA[2 * q + 1], wv.y, vA);
                    fma2(accB[2 * q],     wv.x, vB);
                    fma2(accB[2 * q + 1], wv.y, vB);
                }
                #pragma unroll
                for (int q = 4; q < 8; q++) {
                    ulonglong2 wv = wpM[q - 4];
                    fma2(accA[2 * q],     wv.x, vA);
                    fma2(accA[2 * q + 1], wv.y, vA);
                    fma2(accB[2 * q],     wv.x, vB);
                    fma2(accB[2 * q + 1], wv.y, vB);
                }
                wpP += wstep; wpM += wstep;
            }

            #pragma unroll
            for (int j = 0; j < 4; j++) { p0[j] = q0[j]; p1[j] = q1[j]; }
            ptl += 2 * HW; ptr_ += 2 * HW; pbl += 2 * HW; pbr += 2 * HW;
        }

        // drain: last two channels (no prefetch)
        #pragma unroll
        for (int d = 0; d < 2; d++) {
            float* pv = d ? p1 : p0;
            float vgath = c_tl * pv[0] + c_tr * pv[1]
                        + c_bl * pv[2] + c_br * pv[3];
            float voth = __shfl_xor_sync(0xffffffffu, vgath, 16);
            float vAf = half ? voth : vgath;
            float vBf = half ? vgath : voth;
            unsigned long long vA = pack2(vAf);
            unsigned long long vB = pack2(vBf);
            #pragma unroll
            for (int q = 0; q < 4; q++) {
                ulonglong2 wv = wpP[q];
                fma2(accA[2 * q],     wv.x, vA);
                fma2(accA[2 * q + 1], wv.y, vA);
                fma2(accB[2 * q],     wv.x, vB);
                fma2(accB[2 * q + 1], wv.y, vB);
            }
            #pragma unroll
            for (int q = 4; q < 8; q++) {
                ulonglong2 wv = wpM[q - 4];
                fma2(accA[2 * q],     wv.x, vA);
                fma2(accA[2 * q + 1], wv.y, vA);
                fma2(accB[2 * q],     wv.x, vB);
                fma2(accB[2 * q + 1], wv.y, vB);
            }
            wpP += wstep; wpM += wstep;
        }
    }

    const int pA = blockIdx.x * 256 + wid * 32 + l16;
    const int pB = pA + 16;
    const int bA = pA / HW, rA = pA % HW;
    const int bB = pB / HW, rB = pB % HW;
    float* base = (c0 == 0) ? out : g_part;
    float* opA = base + (size_t)bA * OO * HW + rA;
    float* opB = base + (size_t)bB * OO * HW + rB;
    const int jx = half << 2;
    #pragma unroll
    for (int q = 0; q < 8; q++) {
        int ob = 32 * half + 4 * (q ^ jx);
        float b0 = 0.f, b1 = 0.f, b2 = 0.f, b3 = 0.f;
        if (c0 == 0) {
            b0 = cb[ob + 0]; b1 = cb[ob + 1];
            b2 = cb[ob + 2]; b3 = cb[ob + 3];
        }
        opA[(size_t)(ob + 0) * HW] = lo32(accA[2 * q])     + b0;
        opA[(size_t)(ob + 1) * HW] = hi32(accA[2 * q])     + b1;
        opA[(size_t)(ob + 2) * HW] = lo32(accA[2 * q + 1]) + b2;
        opA[(size_t)(ob + 3) * HW] = hi32(accA[2 * q + 1]) + b3;
        opB[(size_t)(ob + 0) * HW] = lo32(accB[2 * q])     + b0;
        opB[(size_t)(ob + 1) * HW] = hi32(accB[2 * q])     + b1;
        opB[(size_t)(ob + 2) * HW] = lo32(accB[2 * q + 1]) + b2;
        opB[(size_t)(ob + 3) * HW] = hi32(accB[2 * q + 1]) + b3;
    }
}

// ---------------------------------------------------------------------------
// Kernel 3: out += g_part  (vectorized, ~57MB traffic)
// ---------------------------------------------------------------------------
__global__ void __launch_bounds__(256) k_combine(float* __restrict__ out)
{
    int i = blockIdx.x * 256 + threadIdx.x;
    float4 a = ((float4*)out)[i];
    float4 b = ((const float4*)g_part)[i];
    a.x += b.x; a.y += b.y; a.z += b.z; a.w += b.w;
    ((float4*)out)[i] = a;
}

extern "C" void kernel_launch(void* const* d_in, const int* in_sizes, int n_in,
                              void* d_out, int out_size) {
    const float* x  = (const float*)d_in[0];
    const float* ow = (const float*)d_in[1];
    const float* ob = (const float*)d_in[2];
    const float* mw = (const float*)d_in[3];
    const float* mb = (const float*)d_in[4];
    const float* cw = (const float*)d_in[5];
    const float* cb = (const float*)d_in[6];
    float* out = (float*)d_out;

    const int smem1 = CH * 9 * 28 * 4;       // 32256 B
    const int smem2 = CH * NN * OO * 4;      // 73728 B
    cudaFuncSetAttribute(k_offconv, cudaFuncAttributeMaxDynamicSharedMemorySize, smem1);
    cudaFuncSetAttribute(k_deform,  cudaFuncAttributeMaxDynamicSharedMemorySize, smem2);

    dim3 g1((PIXELS / 2) / 128, 2);
    k_offconv<<<g1, 128, smem1>>>(x, ow, ob, mw, mb);
    dim3 g2(PIXELS / 256, 2);
    k_deform<<<g2, 256, smem2>>>(x, cw, cb, out);
    k_combine<<<(PIXELS * OO / 4) / 256, 256>>>(out);
}

// round 7
// speedup vs baseline: 1.4549x; 1.2713x over previous
#include <cuda_runtime.h>
#include <cuda_bf16.h>
#include <math.h>
#include <cstdint>

#define BB 8
#define CC 64
#define OO 64
#define HH 96
#define WW 96
#define NN 9
#define HW (HH*WW)            // 9216
#define PIXELS (BB*HH*WW)     // 73728
#define SCR_CH 27
#define CH 32                 // offconv channels per K-split

// scratch planes [ch][pixel]: partial sums from the two offconv channel halves
__device__ float g_scr [SCR_CH * PIXELS];   // half 0 (+bias)
__device__ float g_scr2[SCR_CH * PIXELS];   // half 1 (raw)
// prepped B: [tap][o(64)][k(192)] bf16, k = [whi(64) | whi(64) | wlo(64)]
__device__ __align__(16) unsigned short g_Bw[NN * 64 * 192];

// ---------------------------------------------------------------------------
// FFMA2 helpers (offconv)
// ---------------------------------------------------------------------------
__device__ __forceinline__ unsigned long long pack2(float v) {
    unsigned long long r;
    unsigned u = __float_as_uint(v);
    asm("mov.b64 %0, {%1, %1};" : "=l"(r) : "r"(u));
    return r;
}
__device__ __forceinline__ void fma2(unsigned long long &acc,
                                     unsigned long long a,
                                     unsigned long long b) {
    asm("fma.rn.f32x2 %0, %1, %2, %0;" : "+l"(acc) : "l"(a), "l"(b));
}
__device__ __forceinline__ float lo32(unsigned long long v) {
    return __uint_as_float((unsigned)(v & 0xffffffffULL));
}
__device__ __forceinline__ float hi32(unsigned long long v) {
    return __uint_as_float((unsigned)(v >> 32));
}

// bf16 mma: D += A(16x16 row) * B(16x8 col)
__device__ __forceinline__ void mma_bf16(float* d, const uint32_t* a,
                                         uint32_t b0, uint32_t b1) {
    asm volatile(
        "mma.sync.aligned.m16n8k16.row.col.f32.bf16.bf16.f32 "
        "{%0,%1,%2,%3}, {%4,%5,%6,%7}, {%8,%9}, {%0,%1,%2,%3};"
        : "+f"(d[0]), "+f"(d[1]), "+f"(d[2]), "+f"(d[3])
        : "r"(a[0]), "r"(a[1]), "r"(a[2]), "r"(a[3]), "r"(b0), "r"(b1));
}

// ---------------------------------------------------------------------------
// Kernel P: build B image. w = conv_w[o][c][tap]; whi = bf16(w),
// wlo = bf16(w - whi). k layout [whi | whi | wlo].
// ---------------------------------------------------------------------------
__global__ void __launch_bounds__(256) k_prepw(const float* __restrict__ cw)
{
    int i = blockIdx.x * 256 + threadIdx.x;    // 9*64*192 = 110592 = 432*256
    int n = i / (64 * 192);
    int rr = i % (64 * 192);
    int o = rr / 192;
    int k = rr % 192;
    int c = k & 63;
    float wv = cw[(o * CC + c) * NN + n];
    __nv_bfloat16 hi = __float2bfloat16(wv);
    __nv_bfloat16 val = (k < 128) ? hi
                      : __float2bfloat16(wv - __bfloat162float(hi));
    unsigned short u; memcpy(&u, &val, 2);
    g_Bw[i] = u;
}

// ---------------------------------------------------------------------------
// Kernel 1: 3x3 conv, 27 outputs, K-split over channel halves (unchanged).
// ---------------------------------------------------------------------------
__global__ void __launch_bounds__(128, 4) k_offconv(
    const float* __restrict__ x,
    const float* __restrict__ ow, const float* __restrict__ ob,
    const float* __restrict__ mw, const float* __restrict__ mb)
{
    extern __shared__ float ws[];   // 288*28 floats = 32256 B
    const int tid = threadIdx.x;
    const int c0 = blockIdx.y * CH;

    for (int i = tid; i < CH * 9 * 28; i += 128) {
        int ck = i / 28, ch = i % 28;
        int c = ck / 9, k = ck % 9;
        float v = 0.f;
        if (ch < 18)      v = ow[(ch * CC + c0 + c) * 9 + k];
        else if (ch < 27) v = mw[((ch - 18) * CC + c0 + c) * 9 + k];
        ws[i] = v;
    }
    __syncthreads();

    const int p0 = blockIdx.x * 128 + tid;
    const int p1 = p0 + PIXELS / 2;

    const int b0 = p0 / HW, r0 = p0 % HW, h0 = r0 / WW, w0 = r0 % WW;
    const int b1 = p1 / HW, r1 = p1 % HW, h1 = r1 / WW, w1 = r1 % WW;

    int offA[9], offB[9];
    #pragma unroll
    for (int k = 0; k < 9; k++) {
        int dh = k / 3 - 1, dw = k % 3 - 1;
        int ihA = h0 + dh, iwA = w0 + dw;
        int ihB = h1 + dh, iwB = w1 + dw;
        offA[k] = ((unsigned)ihA < HH && (unsigned)iwA < WW) ? ihA * WW + iwA : -1;
        offB[k] = ((unsigned)ihB < HH && (unsigned)iwB < WW) ? ihB * WW + iwB : -1;
    }

    unsigned long long accA[14], accB[14];
    #pragma unroll
    for (int j = 0; j < 14; j++) { accA[j] = 0ULL; accB[j] = 0ULL; }

    const float* xa = x + (size_t)b0 * CC * HW + (size_t)c0 * HW;
    const float* xb = x + (size_t)b1 * CC * HW + (size_t)c0 * HW;
    const ulonglong2* wbase = (const ulonglong2*)ws;

    #pragma unroll 1
    for (int c = 0; c < CH; c++) {
        const float* xac = xa + c * HW;
        const float* xbc = xb + c * HW;
        const ulonglong2* wc = wbase + c * 9 * 7;
        #pragma unroll
        for (int k = 0; k < 9; k++) {
            float vA = (offA[k] >= 0) ? __ldg(xac + offA[k]) : 0.f;
            float vB = (offB[k] >= 0) ? __ldg(xbc + offB[k]) : 0.f;
            unsigned long long a2 = pack2(vA);
            unsigned long long b2 = pack2(vB);
            #pragma unroll
            for (int q = 0; q < 7; q++) {
                ulonglong2 wv = wc[k * 7 + q];
                fma2(accA[2 * q],     wv.x, a2);
                fma2(accA[2 * q + 1], wv.y, a2);
                fma2(accB[2 * q],     wv.x, b2);
                fma2(accB[2 * q + 1], wv.y, b2);
            }
        }
    }

    float* dst = (c0 == 0) ? g_scr : g_scr2;
    #pragma unroll
    for (int j = 0; j < 14; j++) {
        int ch0 = 2 * j, ch1 = 2 * j + 1;
        if (ch0 < 27) {
            float bias = 0.f;
            if (c0 == 0) bias = (ch0 < 18) ? ob[ch0] : mb[ch0 - 18];
            dst[ch0 * PIXELS + p0] = lo32(accA[j]) + bias;
            dst[ch0 * PIXELS + p1] = lo32(accB[j]) + bias;
        }
        if (ch1 < 27) {
            float bias = 0.f;
            if (c0 == 0) bias = (ch1 < 18) ? ob[ch1] : mb[ch1 - 18];
            dst[ch1 * PIXELS + p0] = hi32(accA[j]) + bias;
            dst[ch1 * PIXELS + p1] = hi32(accB[j]) + bias;
        }
    }
}

// ---------------------------------------------------------------------------
// Kernel 2 (v7, mma.sync bf16): CTA = 128 threads = 128 pixels.
// Per tap: sample 64ch -> split hi/lo -> SMEM A (128 x 128 bf16, stride 130);
// B[o][k] (64 x 192, stride 198) copied from g_Bw. 12 m16n8k16 K-steps:
//   s 0..3: A cols  0..63 (vhi) x B k  0..63  (whi)
//   s 4..7: A cols 64..127(vlo) x B k 64..127 (whi)
//   s 8..11:A cols  0..63 (vhi) x B k 128..191(wlo)
// Accumulators (2 m-tiles x 8 n-tiles x 4 f32) persist across taps.
// ---------------------------------------------------------------------------
#define AS 130    // A row stride in bf16 (65 words; 65 mod 32 = 1)
#define BS 198    // B row stride in bf16 (99 words; 99 mod 32 = 3)

__global__ void __launch_bounds__(128, 3) k_deform_mma(
    const float* __restrict__ x, const float* __restrict__ cb,
    float* __restrict__ out)
{
    extern __shared__ unsigned short sm[];
    unsigned short* Asm = sm;                 // 128*130*2 = 33280 B
    unsigned short* Bsm = sm + 128 * AS;      // 64*198*2  = 25344 B

    const int tid = threadIdx.x;
    const int wid = tid >> 5;
    const int lane = tid & 31;
    const int g = lane >> 2;      // fragment group 0..7
    const int q = lane & 3;

    const int p = blockIdx.x * 128 + tid;
    const int b = p / HW, r = p % HW;
    const int h = r / WW, w = r % WW;
    const float* xg = x + (size_t)b * CC * HW;

    float acc[2][8][4];
    #pragma unroll
    for (int mt = 0; mt < 2; mt++)
        #pragma unroll
        for (int nt = 0; nt < 8; nt++)
            #pragma unroll
            for (int e = 0; e < 4; e++) acc[mt][nt][e] = 0.f;

    #pragma unroll 1
    for (int n = 0; n < NN; n++) {
        // ---- copy B tile for this tap (6144 uints, 48/thread) ----
        {
            const uint32_t* src = (const uint32_t*)g_Bw + n * 6144;
            #pragma unroll
            for (int j = 0; j < 48; j++) {
                int i = tid + 128 * j;
                int row = i / 96, col = i % 96;     // 96 uints per 192-bf16 row
                ((uint32_t*)(Bsm + row * BS))[col] = __ldg(src + i);
            }
        }

        // ---- sampling coordinates ----
        float offx = g_scr[n * PIXELS + p]        + g_scr2[n * PIXELS + p];
        float offy = g_scr[(9 + n) * PIXELS + p]  + g_scr2[(9 + n) * PIXELS + p];
        float mraw = g_scr[(18 + n) * PIXELS + p] + g_scr2[(18 + n) * PIXELS + p];
        float m = 1.f / (1.f + __expf(-mraw));

        float px = offx + (float)(h + 1) + (float)(n / 3 - 1);
        float py = offy + (float)(w + 1) + (float)(n % 3 - 1);

        float flx = floorf(px), fly = floorf(py);
        int tlx = max(min((int)flx, 97), 0);
        int brx = max(min((int)flx + 1, 97), 0);
        int tly = max(min((int)fly, 97), 0);
        int bry = max(min((int)fly + 1, 97), 0);
        float pcx = fminf(fmaxf(px, 0.f), 97.f);
        float pcy = fminf(fmaxf(py, 0.f), 97.f);

        float axt = 1.f + ((float)tlx - pcx);
        float axb = 1.f - ((float)brx - pcx);
        float ayt = 1.f + ((float)tly - pcy);
        float ayb = 1.f - ((float)bry - pcy);

        float c_tl = axt * ayt * m;
        float c_tr = axt * ayb * m;
        float c_bl = axb * ayt * m;
        float c_br = axb * ayb * m;

        bool vtx = (tlx >= 1 && tlx <= 96);
        bool vbx = (brx >= 1 && brx <= 96);
        bool vty = (tly >= 1 && tly <= 96);
        bool vby = (bry >= 1 && bry <= 96);

        int a_tl = (tlx - 1) * WW + (tly - 1);
        int a_tr = (tlx - 1) * WW + (bry - 1);
        int a_bl = (brx - 1) * WW + (tly - 1);
        int a_br = (brx - 1) * WW + (bry - 1);
        if (!(vtx && vty)) { c_tl = 0.f; a_tl = 0; }
        if (!(vtx && vby)) { c_tr = 0.f; a_tr = 0; }
        if (!(vbx && vty)) { c_bl = 0.f; a_bl = 0; }
        if (!(vbx && vby)) { c_br = 0.f; a_br = 0; }

        // ---- sample 64 channels, split hi/lo, store A row = tid ----
        uint32_t* arow = (uint32_t*)(Asm + tid * AS);
        #pragma unroll 2
        for (int j = 0; j < 32; j++) {
            const float* x0 = xg + (size_t)(2 * j) * HW;
            const float* x1 = x0 + HW;
            float v0 = c_tl * __ldg(x0 + a_tl) + c_tr * __ldg(x0 + a_tr)
                     + c_bl * __ldg(x0 + a_bl) + c_br * __ldg(x0 + a_br);
            float v1 = c_tl * __ldg(x1 + a_tl) + c_tr * __ldg(x1 + a_tr)
                     + c_bl * __ldg(x1 + a_bl) + c_br * __ldg(x1 + a_br);
            uint32_t hp;
            asm("cvt.rn.satfinite.bf16x2.f32 %0, %1, %2;"
                : "=r"(hp) : "f"(v1), "f"(v0));   // lower half = v0
            float h0 = __uint_as_float(hp << 16);
            float h1 = __uint_as_float(hp & 0xffff0000u);
            float l0 = v0 - h0, l1 = v1 - h1;
            uint32_t lp;
            asm("cvt.rn.satfinite.bf16x2.f32 %0, %1, %2;"
                : "=r"(lp) : "f"(l1), "f"(l0));
            arow[j] = hp;          // cols 2j, 2j+1
            arow[32 + j] = lp;     // cols 64+2j, 64+2j+1
        }
        __syncthreads();

        // ---- 12 K-steps of m16n8k16 ----
        #pragma unroll
        for (int s = 0; s < 12; s++) {
            const int acol = (s < 8) ? s * 16 : (s - 8) * 16;
            const int bk = s * 16;
            uint32_t a[2][4];
            #pragma unroll
            for (int mt = 0; mt < 2; mt++) {
                int r0 = wid * 32 + mt * 16 + g;
                const unsigned short* A0 = Asm + r0 * AS + acol + q * 2;
                const unsigned short* A1 = A0 + 8 * AS;
                a[mt][0] = *(const uint32_t*)A0;
                a[mt][1] = *(const uint32_t*)A1;
                a[mt][2] = *(const uint32_t*)(A0 + 8);
                a[mt][3] = *(const uint32_t*)(A1 + 8);
            }
            #pragma unroll
            for (int nt = 0; nt < 8; nt++) {
                const unsigned short* Bp = Bsm + (nt * 8 + g) * BS + bk + q * 2;
                uint32_t b0 = *(const uint32_t*)Bp;
                uint32_t b1 = *(const uint32_t*)(Bp + 8);
                mma_bf16(acc[0][nt], a[0], b0, b1);
                mma_bf16(acc[1][nt], a[1], b0, b1);
            }
        }
        __syncthreads();
    }

    // ---- epilogue: D(16x8) rows = pixels, cols = outputs ----
    #pragma unroll
    for (int mt = 0; mt < 2; mt++) {
        int prow = blockIdx.x * 128 + wid * 32 + mt * 16 + g;
        int pb0 = prow / HW,      pr0 = prow % HW;
        int pb1 = (prow + 8) / HW, pr1 = (prow + 8) % HW;
        float* o0 = out + (size_t)pb0 * OO * HW + pr0;
        float* o1 = out + (size_t)pb1 * OO * HW + pr1;
        #pragma unroll
        for (int nt = 0; nt < 8; nt++) {
            int oc = nt * 8 + q * 2;
            float bb0 = cb[oc], bb1 = cb[oc + 1];
            o0[(size_t)oc * HW]       = acc[mt][nt][0] + bb0;
            o0[(size_t)(oc + 1) * HW] = acc[mt][nt][1] + bb1;
            o1[(size_t)oc * HW]       = acc[mt][nt][2] + bb0;
            o1[(size_t)(oc + 1) * HW] = acc[mt][nt][3] + bb1;
        }
    }
}

extern "C" void kernel_launch(void* const* d_in, const int* in_sizes, int n_in,
                              void* d_out, int out_size) {
    const float* x  = (const float*)d_in[0];
    const float* ow = (const float*)d_in[1];
    const float* ob = (const float*)d_in[2];
    const float* mw = (const float*)d_in[3];
    const float* mb = (const float*)d_in[4];
    const float* cw = (const float*)d_in[5];
    const float* cb = (const float*)d_in[6];
    float* out = (float*)d_out;

    const int smem1 = CH * 9 * 28 * 4;                    // 32256 B
    const int smem2 = (128 * AS + 64 * BS) * 2;           // 58624 B
    cudaFuncSetAttribute(k_offconv,    cudaFuncAttributeMaxDynamicSharedMemorySize, smem1);
    cudaFuncSetAttribute(k_deform_mma, cudaFuncAttributeMaxDynamicSharedMemorySize, smem2);

    k_prepw<<<432, 256>>>(cw);
    dim3 g1((PIXELS / 2) / 128, 2);
    k_offconv<<<g1, 128, smem1>>>(x, ow, ob, mw, mb);
    k_deform_mma<<<PIXELS / 128, 128, smem2>>>(x, cb, out);
}

// round 9
// speedup vs baseline: 1.7104x; 1.1757x over previous
#include <cuda_runtime.h>
#include <cuda_bf16.h>
#include <math.h>
#include <cstdint>

#define BB 8
#define CC 64
#define OO 64
#define HH 96
#define WW 96
#define NN 9
#define HW (HH*WW)            // 9216
#define PIXELS (BB*HH*WW)     // 73728
#define SCR_CH 27

// offset (18) + modulation-raw (9) planes, layout [ch][pixel], bias included
__device__ float g_scr[SCR_CH * PIXELS];
// prepped B for deform: [tap][o(64)][k(192)] bf16, k = [whi | whi | wlo]
__device__ __align__(16) unsigned short g_Bw[NN * 64 * 192];
// prepped B for offconv: [tap][o(32, 27 used)][k(192)] bf16
__device__ __align__(16) unsigned short g_Bw2[NN * 32 * 192];

// bf16 mma: D += A(16x16 row) * B(16x8 col)
__device__ __forceinline__ void mma_bf16(float* d, const uint32_t* a,
                                         uint32_t b0, uint32_t b1) {
    asm volatile(
        "mma.sync.aligned.m16n8k16.row.col.f32.bf16.bf16.f32 "
        "{%0,%1,%2,%3}, {%4,%5,%6,%7}, {%8,%9}, {%0,%1,%2,%3};"
        : "+f"(d[0]), "+f"(d[1]), "+f"(d[2]), "+f"(d[3])
        : "r"(a[0]), "r"(a[1]), "r"(a[2]), "r"(a[3]), "r"(b0), "r"(b1));
}

// ---------------------------------------------------------------------------
// Kernel P: build both B images (hi/lo split, k layout [whi|whi|wlo]).
//   i <  110592: deform  B, w = cw[o][c][tap],      64 rows
//   i >= 110592: offconv B, w = ow/mw[o][c][tap],   32 rows (o>=27 -> 0)
// ---------------------------------------------------------------------------
__global__ void __launch_bounds__(256) k_prepw(
    const float* __restrict__ cw,
    const float* __restrict__ ow, const float* __restrict__ mw)
{
    int i = blockIdx.x * 256 + threadIdx.x;     // 648*256 = 165888
    float wv;
    unsigned short* dst;
    int k;
    if (i < NN * 64 * 192) {
        int n = i / (64 * 192);
        int rr = i % (64 * 192);
        int o = rr / 192;
        k = rr % 192;
        int c = k & 63;
        wv = cw[(o * CC + c) * NN + n];
        dst = g_Bw + i;
    } else {
        int j = i - NN * 64 * 192;              // 9*32*192 = 55296
        int n = j / (32 * 192);
        int rr = j % (32 * 192);
        int o = rr / 192;
        k = rr % 192;
        int c = k & 63;
        wv = (o < 18) ? ow[(o * CC + c) * 9 + n]
           : (o < 27) ? mw[((o - 18) * CC + c) * 9 + n] : 0.f;
        dst = g_Bw2 + j;
    }
    __nv_bfloat16 hi = __float2bfloat16(wv);
    __nv_bfloat16 val = (k < 128) ? hi
                      : __float2bfloat16(wv - __bfloat162float(hi));
    unsigned short u; memcpy(&u, &val, 2);
    *dst = u;
}

#define AS 130    // A row stride in bf16 (65 words; 65 mod 32 = 1)
#define BS 200    // B row stride in bf16 (100 words; 16B-aligned rows)

// ---------------------------------------------------------------------------
// Kernel 1 (v9, mma): offset/mod conv as 9-tap GEMM.
// CTA = 128 px. A per tap: x at shifted window (coalesced), hi/lo split.
// B: 32 x 192. 12 K-steps x 4 n-tiles. Epilogue -> g_scr[ch][pixel] + bias
// (written via the DEVICE symbol -- round 8 bug was passing g_scr from host).
// ---------------------------------------------------------------------------
__global__ void __launch_bounds__(128, 4) k_offconv_mma(
    const float* __restrict__ x,
    const float* __restrict__ ob, const float* __restrict__ mb)
{
    extern __shared__ unsigned short sm[];
    unsigned short* Asm = sm;                 // 128*130*2 = 33280 B
    unsigned short* Bsm = sm + 128 * AS;      // 32*200*2  = 12800 B

    const int tid = threadIdx.x;
    const int wid = tid >> 5;
    const int lane = tid & 31;
    const int g = lane >> 2;
    const int q = lane & 3;

    const int p = blockIdx.x * 128 + tid;
    const int b = p / HW, r = p % HW;
    const int h = r / WW, w = r % WW;
    const float* xg = x + (size_t)b * CC * HW;

    float acc[2][4][4];
    #pragma unroll
    for (int mt = 0; mt < 2; mt++)
        #pragma unroll
        for (int nt = 0; nt < 4; nt++)
            #pragma unroll
            for (int e = 0; e < 4; e++) acc[mt][nt][e] = 0.f;

    #pragma unroll 1
    for (int n = 0; n < NN; n++) {
        // ---- B tile: 32 rows x 192 bf16 = 768 uint4, 6 per thread ----
        {
            const uint4* src = (const uint4*)(g_Bw2 + n * 32 * 192);
            #pragma unroll
            for (int j = 0; j < 6; j++) {
                int i = tid + 128 * j;
                int row = i / 24, c4 = i % 24;
                ((uint4*)(Bsm + row * BS))[c4] = __ldg(src + i);
            }
        }

        // ---- A fill: shifted-window loads (coalesced), hi/lo split ----
        int dh = n / 3 - 1, dw = n % 3 - 1;
        int ih = h + dh, iw = w + dw;
        int off = ((unsigned)ih < HH && (unsigned)iw < WW) ? ih * WW + iw : -1;
        const float* xs = xg + off;
        uint32_t* arow = (uint32_t*)(Asm + tid * AS);
        #pragma unroll 4
        for (int j = 0; j < 32; j++) {
            float v0 = 0.f, v1 = 0.f;
            if (off >= 0) {
                v0 = __ldg(xs + (size_t)(2 * j) * HW);
                v1 = __ldg(xs + (size_t)(2 * j + 1) * HW);
            }
            uint32_t hp;
            asm("cvt.rn.satfinite.bf16x2.f32 %0, %1, %2;"
                : "=r"(hp) : "f"(v1), "f"(v0));
            float h0 = __uint_as_float(hp << 16);
            float h1 = __uint_as_float(hp & 0xffff0000u);
            float l0 = v0 - h0, l1 = v1 - h1;
            uint32_t lp;
            asm("cvt.rn.satfinite.bf16x2.f32 %0, %1, %2;"
                : "=r"(lp) : "f"(l1), "f"(l0));
            arow[j] = hp;
            arow[32 + j] = lp;
        }
        __syncthreads();

        // ---- 12 K-steps of m16n8k16, 4 n-tiles ----
        #pragma unroll
        for (int s = 0; s < 12; s++) {
            const int acol = (s < 8) ? s * 16 : (s - 8) * 16;
            const int bk = s * 16;
            uint32_t a[2][4];
            #pragma unroll
            for (int mt = 0; mt < 2; mt++) {
                int r0 = wid * 32 + mt * 16 + g;
                const unsigned short* A0 = Asm + r0 * AS + acol + q * 2;
                const unsigned short* A1 = A0 + 8 * AS;
                a[mt][0] = *(const uint32_t*)A0;
                a[mt][1] = *(const uint32_t*)A1;
                a[mt][2] = *(const uint32_t*)(A0 + 8);
                a[mt][3] = *(const uint32_t*)(A1 + 8);
            }
            #pragma unroll
            for (int nt = 0; nt < 4; nt++) {
                const unsigned short* Bp = Bsm + (nt * 8 + g) * BS + bk + q * 2;
                uint32_t b0 = *(const uint32_t*)Bp;
                uint32_t b1 = *(const uint32_t*)(Bp + 8);
                mma_bf16(acc[0][nt], a[0], b0, b1);
                mma_bf16(acc[1][nt], a[1], b0, b1);
            }
        }
        __syncthreads();
    }

    // ---- epilogue -> g_scr[oc][pixel] (+bias), oc < 27 ----
    #pragma unroll
    for (int mt = 0; mt < 2; mt++) {
        int prow = blockIdx.x * 128 + wid * 32 + mt * 16 + g;
        #pragma unroll
        for (int nt = 0; nt < 4; nt++) {
            int oc = nt * 8 + q * 2;
            if (oc < 27) {
                float bias = (oc < 18) ? ob[oc] : mb[oc - 18];
                g_scr[(size_t)oc * PIXELS + prow]     = acc[mt][nt][0] + bias;
                g_scr[(size_t)oc * PIXELS + prow + 8] = acc[mt][nt][2] + bias;
            }
            if (oc + 1 < 27) {
                float bias = (oc + 1 < 18) ? ob[oc + 1] : mb[oc - 17];
                g_scr[(size_t)(oc + 1) * PIXELS + prow]     = acc[mt][nt][1] + bias;
                g_scr[(size_t)(oc + 1) * PIXELS + prow + 8] = acc[mt][nt][3] + bias;
            }
        }
    }
}

// ---------------------------------------------------------------------------
// Kernel 2 (v9, mma.sync bf16): deformable sampling + contraction.
// Round 7 winner structure, single g_scr read, uint4 B copy (BS=200).
// ---------------------------------------------------------------------------
__global__ void __launch_bounds__(128, 3) k_deform_mma(
    const float* __restrict__ x, const float* __restrict__ cb,
    float* __restrict__ out)
{
    extern __shared__ unsigned short sm[];
    unsigned short* Asm = sm;                 // 128*130*2 = 33280 B
    unsigned short* Bsm = sm + 128 * AS;      // 64*200*2  = 25600 B

    const int tid = threadIdx.x;
    const int wid = tid >> 5;
    const int lane = tid & 31;
    const int g = lane >> 2;
    const int q = lane & 3;

    const int p = blockIdx.x * 128 + tid;
    const int b = p / HW, r = p % HW;
    const int h = r / WW, w = r % WW;
    const float* xg = x + (size_t)b * CC * HW;

    float acc[2][8][4];
    #pragma unroll
    for (int mt = 0; mt < 2; mt++)
        #pragma unroll
        for (int nt = 0; nt < 8; nt++)
            #pragma unroll
            for (int e = 0; e < 4; e++) acc[mt][nt][e] = 0.f;

    #pragma unroll 1
    for (int n = 0; n < NN; n++) {
        // ---- B tile: 64 rows x 192 bf16 = 1536 uint4, 12 per thread ----
        {
            const uint4* src = (const uint4*)(g_Bw + n * 64 * 192);
            #pragma unroll
            for (int j = 0; j < 12; j++) {
                int i = tid + 128 * j;
                int row = i / 24, c4 = i % 24;
                ((uint4*)(Bsm + row * BS))[c4] = __ldg(src + i);
            }
        }

        // ---- sampling coordinates ----
        float offx = g_scr[n * PIXELS + p];
        float offy = g_scr[(9 + n) * PIXELS + p];
        float mraw = g_scr[(18 + n) * PIXELS + p];
        float m = 1.f / (1.f + __expf(-mraw));

        float px = offx + (float)(h + 1) + (float)(n / 3 - 1);
        float py = offy + (float)(w + 1) + (float)(n % 3 - 1);

        float flx = floorf(px), fly = floorf(py);
        int tlx = max(min((int)flx, 97), 0);
        int brx = max(min((int)flx + 1, 97), 0);
        int tly = max(min((int)fly, 97), 0);
        int bry = max(min((int)fly + 1, 97), 0);
        float pcx = fminf(fmaxf(px, 0.f), 97.f);
        float pcy = fminf(fmaxf(py, 0.f), 97.f);

        float axt = 1.f + ((float)tlx - pcx);
        float axb = 1.f - ((float)brx - pcx);
        float ayt = 1.f + ((float)tly - pcy);
        float ayb = 1.f - ((float)bry - pcy);

        float c_tl = axt * ayt * m;
        float c_tr = axt * ayb * m;
        float c_bl = axb * ayt * m;
        float c_br = axb * ayb * m;

        bool vtx = (tlx >= 1 && tlx <= 96);
        bool vbx = (brx >= 1 && brx <= 96);
        bool vty = (tly >= 1 && tly <= 96);
        bool vby = (bry >= 1 && bry <= 96);

        int a_tl = (tlx - 1) * WW + (tly - 1);
        int a_tr = (tlx - 1) * WW + (bry - 1);
        int a_bl = (brx - 1) * WW + (tly - 1);
        int a_br = (brx - 1) * WW + (bry - 1);
        if (!(vtx && vty)) { c_tl = 0.f; a_tl = 0; }
        if (!(vtx && vby)) { c_tr = 0.f; a_tr = 0; }
        if (!(vbx && vty)) { c_bl = 0.f; a_bl = 0; }
        if (!(vbx && vby)) { c_br = 0.f; a_br = 0; }

        // ---- sample 64 channels, split hi/lo, store A row = tid ----
        uint32_t* arow = (uint32_t*)(Asm + tid * AS);
        #pragma unroll 2
        for (int j = 0; j < 32; j++) {
            const float* x0 = xg + (size_t)(2 * j) * HW;
            const float* x1 = x0 + HW;
            float v0 = c_tl * __ldg(x0 + a_tl) + c_tr * __ldg(x0 + a_tr)
                     + c_bl * __ldg(x0 + a_bl) + c_br * __ldg(x0 + a_br);
            float v1 = c_tl * __ldg(x1 + a_tl) + c_tr * __ldg(x1 + a_tr)
                     + c_bl * __ldg(x1 + a_bl) + c_br * __ldg(x1 + a_br);
            uint32_t hp;
            asm("cvt.rn.satfinite.bf16x2.f32 %0, %1, %2;"
                : "=r"(hp) : "f"(v1), "f"(v0));
            float h0 = __uint_as_float(hp << 16);
            float h1 = __uint_as_float(hp & 0xffff0000u);
            float l0 = v0 - h0, l1 = v1 - h1;
            uint32_t lp;
            asm("cvt.rn.satfinite.bf16x2.f32 %0, %1, %2;"
                : "=r"(lp) : "f"(l1), "f"(l0));
            arow[j] = hp;
            arow[32 + j] = lp;
        }
        __syncthreads();

        // ---- 12 K-steps of m16n8k16, 8 n-tiles ----
        #pragma unroll
        for (int s = 0; s < 12; s++) {
            const int acol = (s < 8) ? s * 16 : (s - 8) * 16;
            const int bk = s * 16;
            uint32_t a[2][4];
            #pragma unroll
            for (int mt = 0; mt < 2; mt++) {
                int r0 = wid * 32 + mt * 16 + g;
                const unsigned short* A0 = Asm + r0 * AS + acol + q * 2;
                const unsigned short* A1 = A0 + 8 * AS;
                a[mt][0] = *(const uint32_t*)A0;
                a[mt][1] = *(const uint32_t*)A1;
                a[mt][2] = *(const uint32_t*)(A0 + 8);
                a[mt][3] = *(const uint32_t*)(A1 + 8);
            }
            #pragma unroll
            for (int nt = 0; nt < 8; nt++) {
                const unsigned short* Bp = Bsm + (nt * 8 + g) * BS + bk + q * 2;
                uint32_t b0 = *(const uint32_t*)Bp;
                uint32_t b1 = *(const uint32_t*)(Bp + 8);
                mma_bf16(acc[0][nt], a[0], b0, b1);
                mma_bf16(acc[1][nt], a[1], b0, b1);
            }
        }
        __syncthreads();
    }

    // ---- epilogue ----
    #pragma unroll
    for (int mt = 0; mt < 2; mt++) {
        int prow = blockIdx.x * 128 + wid * 32 + mt * 16 + g;
        int pb0 = prow / HW,       pr0 = prow % HW;
        int pb1 = (prow + 8) / HW, pr1 = (prow + 8) % HW;
        float* o0 = out + (size_t)pb0 * OO * HW + pr0;
        float* o1 = out + (size_t)pb1 * OO * HW + pr1;
        #pragma unroll
        for (int nt = 0; nt < 8; nt++) {
            int oc = nt * 8 + q * 2;
            float bb0 = cb[oc], bb1 = cb[oc + 1];
            o0[(size_t)oc * HW]       = acc[mt][nt][0] + bb0;
            o0[(size_t)(oc + 1) * HW] = acc[mt][nt][1] + bb1;
            o1[(size_t)oc * HW]       = acc[mt][nt][2] + bb0;
            o1[(size_t)(oc + 1) * HW] = acc[mt][nt][3] + bb1;
        }
    }
}

extern "C" void kernel_launch(void* const* d_in, const int* in_sizes, int n_in,
                              void* d_out, int out_size) {
    const float* x  = (const float*)d_in[0];
    const float* ow = (const float*)d_in[1];
    const float* ob = (const float*)d_in[2];
    const float* mw = (const float*)d_in[3];
    const float* mb = (const float*)d_in[4];
    const float* cw = (const float*)d_in[5];
    const float* cb = (const float*)d_in[6];
    float* out = (float*)d_out;

    const int smem1 = (128 * AS + 32 * BS) * 2;   // 46080 B
    const int smem2 = (128 * AS + 64 * BS) * 2;   // 58880 B
    cudaFuncSetAttribute(k_offconv_mma, cudaFuncAttributeMaxDynamicSharedMemorySize, smem1);
    cudaFuncSetAttribute(k_deform_mma,  cudaFuncAttributeMaxDynamicSharedMemorySize, smem2);

    k_prepw<<<648, 256>>>(cw, ow, mw);
    k_offconv_mma<<<PIXELS / 128, 128, smem1>>>(x, ob, mb);
    k_deform_mma<<<PIXELS / 128, 128, smem2>>>(x, cb, out);
}